// round 1
// baseline (speedup 1.0000x reference)
#include <cuda_runtime.h>
#include <math.h>

#define NATOMS 50000
#define NPAD   50016          // rounded up to 32-node tiles
#define NEDGE  1600000
#define HDIM   128
#define FDIM   64
#define GDIM   50
#define NLAY   3
#define NGRAPH 256
#define TABN   16384
#define DMAXV  8.6603f        // > 5*sqrt(3) = max possible distance
#define TSTEP  (DMAXV / (TABN - 1))
#define TINV   ((TABN - 1) / DMAXV)

// ---- scratch (device globals; no allocation allowed) ----
__device__ float g_h   [NPAD * HDIM];
__device__ float g_xt  [NPAD * FDIM];
__device__ float g_agg [NPAD * FDIM];
__device__ float g_tbuf[NPAD * HDIM];
__device__ float g_d   [NEDGE];
__device__ float g_tab [NLAY * TABN * FDIM];

__device__ __forceinline__ float sspf(float x) {
    // softplus(x) - ln 2, numerically stable
    float sp = fmaxf(x, 0.0f) + log1pf(__expf(-fabsf(x)));
    return sp - 0.69314718055994531f;
}

// ---------------- h = emb[z] ----------------
__global__ void h_init_kernel(const int* __restrict__ z,
                              const float* __restrict__ emb) {
    int i = blockIdx.x * blockDim.x + threadIdx.x;   // one float4 per thread
    if (i >= NATOMS * 32) return;
    int n = i >> 5;
    int c = i & 31;
    ((float4*)g_h)[i] = ((const float4*)emb)[__ldg(z + n) * 32 + c];
}

// ---------------- per-edge distance ----------------
__global__ void edge_d_kernel(const int* __restrict__ ei,
                              const float* __restrict__ pos) {
    int e = blockIdx.x * blockDim.x + threadIdx.x;
    if (e >= NEDGE) return;
    int s = __ldg(ei + e);
    int t = __ldg(ei + NEDGE + e);
    float dx = __ldg(pos + s * 3 + 0) - __ldg(pos + t * 3 + 0);
    float dy = __ldg(pos + s * 3 + 1) - __ldg(pos + t * 3 + 1);
    float dz = __ldg(pos + s * 3 + 2) - __ldg(pos + t * 3 + 2);
    g_d[e] = sqrtf(dx * dx + dy * dy + dz * dz);
}

// ---------------- filter lookup tables ----------------
// One warp builds one (layer, table-row) entry: W(d)*C(d) for 64 channels.
__global__ void build_tab_kernel(const float* __restrict__ mw1,
                                 const float* __restrict__ mb1,
                                 const float* __restrict__ mw2,
                                 const float* __restrict__ mb2) {
    int gwarp = (blockIdx.x * blockDim.x + threadIdx.x) >> 5;
    int lane  = threadIdx.x & 31;
    if (gwarp >= NLAY * TABN) return;
    int layer = gwarp / TABN;
    int ti    = gwarp % TABN;
    float dv  = ti * TSTEP;

    __shared__ float sh[8][64];
    int wl = threadIdx.x >> 5;

    const float offstep = 10.0f / 49.0f;
    const float coeff   = -0.5f / (offstep * offstep);

    // gaussian smearing
    for (int g = lane; g < GDIM; g += 32) {
        float x = dv - g * offstep;
        sh[wl][g] = expf(coeff * x * x);
    }
    __syncwarp();

    const float* w1 = mw1 + layer * GDIM * FDIM;
    const float* b1 = mb1 + layer * FDIM;
    float a0 = __ldg(b1 + 2 * lane);
    float a1 = __ldg(b1 + 2 * lane + 1);
    for (int g = 0; g < GDIM; g++) {
        float e = sh[wl][g];
        a0 = fmaf(e, __ldg(w1 + g * FDIM + 2 * lane),     a0);
        a1 = fmaf(e, __ldg(w1 + g * FDIM + 2 * lane + 1), a1);
    }
    a0 = sspf(a0);
    a1 = sspf(a1);
    __syncwarp();
    sh[wl][2 * lane]     = a0;
    sh[wl][2 * lane + 1] = a1;
    __syncwarp();

    const float* w2 = mw2 + layer * FDIM * FDIM;
    const float* b2 = mb2 + layer * FDIM;
    float c0 = __ldg(b2 + 2 * lane);
    float c1 = __ldg(b2 + 2 * lane + 1);
    for (int f = 0; f < FDIM; f++) {
        float tv = sh[wl][f];
        c0 = fmaf(tv, __ldg(w2 + f * FDIM + 2 * lane),     c0);
        c1 = fmaf(tv, __ldg(w2 + f * FDIM + 2 * lane + 1), c1);
    }
    float C = 0.5f * (cosf(dv * 3.14159265358979323846f / 10.0f) + 1.0f);
    float* dst = g_tab + (layer * TABN + ti) * FDIM;
    dst[2 * lane]     = c0 * C;
    dst[2 * lane + 1] = c1 * C;
}

// ---------------- zero helper ----------------
__global__ void zero_kernel(float* __restrict__ p, int n) {
    for (int i = blockIdx.x * blockDim.x + threadIdx.x; i < n;
         i += gridDim.x * blockDim.x)
        p[i] = 0.0f;
}

// ---------------- node GEMM:  out[n, OUT] = act(in[n, IN] @ w + b) (+resid) ----
// Block: 256 threads, 32-node tile. Thread = (og, np): og in [0,16) covers
// OUT/16 consecutive outputs, np in [0,16) covers 2 nodes. Weights streamed
// through shared in 32-row K-chunks.
template <int IN, int OUT, bool ACT, bool RESID>
__global__ void __launch_bounds__(256) node_gemm(
    const float* __restrict__ in, const float* __restrict__ w,
    const float* __restrict__ b, float* __restrict__ out) {
    constexpr int TILE = 32;
    constexpr int KT   = 32;
    constexpr int OPT  = OUT / 16;     // outputs per thread
    constexpr int NCH  = IN / KT;

    __shared__ float sw[KT * OUT];
    __shared__ float sin_[TILE * (IN + 1)];

    int t  = threadIdx.x;
    int og = t & 15;
    int np = t >> 4;
    int n0 = np * 2;
    int n1 = n0 + 1;

    float bias[OPT];
#pragma unroll
    for (int o = 0; o < OPT; o++)
        bias[o] = b ? __ldg(b + og * OPT + o) : 0.0f;

    const int ntiles = NPAD / TILE;
    for (int tile = blockIdx.x; tile < ntiles; tile += gridDim.x) {
        const float* inb = in + tile * TILE * IN;
        __syncthreads();
        for (int i = t; i < TILE * IN / 4; i += 256) {
            int n  = i / (IN / 4);
            int k4 = i % (IN / 4);
            float4 v = ((const float4*)inb)[i];
            float* p = sin_ + n * (IN + 1) + k4 * 4;
            p[0] = v.x; p[1] = v.y; p[2] = v.z; p[3] = v.w;
        }

        float acc0[OPT], acc1[OPT];
#pragma unroll
        for (int o = 0; o < OPT; o++) { acc0[o] = bias[o]; acc1[o] = bias[o]; }

#pragma unroll 1
        for (int ch = 0; ch < NCH; ch++) {
            __syncthreads();
            for (int i = t; i < KT * OUT / 4; i += 256)
                ((float4*)sw)[i] = ((const float4*)(w + ch * KT * OUT))[i];
            __syncthreads();
#pragma unroll
            for (int k = 0; k < KT; k++) {
                float a0 = sin_[n0 * (IN + 1) + ch * KT + k];
                float a1 = sin_[n1 * (IN + 1) + ch * KT + k];
                const float* wr = sw + k * OUT + og * OPT;
#pragma unroll
                for (int o = 0; o < OPT; o += 4) {
                    float4 wv = *(const float4*)(wr + o);
                    acc0[o + 0] = fmaf(a0, wv.x, acc0[o + 0]);
                    acc0[o + 1] = fmaf(a0, wv.y, acc0[o + 1]);
                    acc0[o + 2] = fmaf(a0, wv.z, acc0[o + 2]);
                    acc0[o + 3] = fmaf(a0, wv.w, acc0[o + 3]);
                    acc1[o + 0] = fmaf(a1, wv.x, acc1[o + 0]);
                    acc1[o + 1] = fmaf(a1, wv.y, acc1[o + 1]);
                    acc1[o + 2] = fmaf(a1, wv.z, acc1[o + 2]);
                    acc1[o + 3] = fmaf(a1, wv.w, acc1[o + 3]);
                }
            }
        }

        float* op0 = out + (tile * TILE + n0) * OUT + og * OPT;
        float* op1 = out + (tile * TILE + n1) * OUT + og * OPT;
#pragma unroll
        for (int o = 0; o < OPT; o++) {
            float v0 = acc0[o], v1 = acc1[o];
            if (ACT)  { v0 = sspf(v0); v1 = sspf(v1); }
            if (RESID){ v0 += op0[o];  v1 += op1[o];  }
            op0[o] = v0;
            op1[o] = v1;
        }
    }
}

// ---------------- edge message + scatter ----------------
// One warp per edge, each lane owns 2 channels (float2).
__global__ void __launch_bounds__(256) edge_msg_kernel(
    const int* __restrict__ ei, const float* __restrict__ tab) {
    int gt   = blockIdx.x * blockDim.x + threadIdx.x;
    int e    = gt >> 5;
    int lane = gt & 31;
    if (e >= NEDGE) return;

    int s = __ldg(ei + e);
    int t = __ldg(ei + NEDGE + e);
    float de = g_d[e];

    float u  = de * TINV;
    int   i0 = (int)u;
    i0 = min(i0, TABN - 2);
    float fr = u - (float)i0;

    const float2* tp = ((const float2*)tab) + i0 * 32 + lane;
    float2 a  = tp[0];
    float2 bb = tp[32];
    float wx = fmaf(fr, bb.x - a.x, a.x);
    float wy = fmaf(fr, bb.y - a.y, a.y);

    float2 xj = ((const float2*)g_xt)[s * 32 + lane];

    float* ap = g_agg + t * 64 + lane * 2;
    atomicAdd(ap,     xj.x * wx);
    atomicAdd(ap + 1, xj.y * wy);
}

// ---------------- readout: per-node scalar + per-graph atomic sum ----------
__global__ void readout_kernel(const float* __restrict__ ow2,
                               const float* __restrict__ ob2,
                               const int* __restrict__ batch,
                               float* __restrict__ out) {
    int gt   = blockIdx.x * blockDim.x + threadIdx.x;
    int n    = gt >> 5;
    int lane = gt & 31;
    if (n >= NATOMS) return;
    float2 v = ((const float2*)g_xt)[n * 32 + lane];
    float2 w = ((const float2*)ow2)[lane];
    float s = v.x * w.x + v.y * w.y;
#pragma unroll
    for (int off = 16; off; off >>= 1)
        s += __shfl_down_sync(0xffffffffu, s, off);
    if (lane == 0)
        atomicAdd(out + __ldg(batch + n), s + __ldg(ob2));
}

extern "C" void kernel_launch(void* const* d_in, const int* in_sizes, int n_in,
                              void* d_out, int out_size) {
    const int*   z     = (const int*)  d_in[0];
    const float* pos   = (const float*)d_in[1];
    const int*   batch = (const int*)  d_in[2];
    const int*   eidx  = (const int*)  d_in[3];
    const float* emb   = (const float*)d_in[4];
    const float* mw1   = (const float*)d_in[5];
    const float* mb1   = (const float*)d_in[6];
    const float* mw2   = (const float*)d_in[7];
    const float* mb2   = (const float*)d_in[8];
    const float* l1w   = (const float*)d_in[9];
    const float* l2w   = (const float*)d_in[10];
    const float* l2b   = (const float*)d_in[11];
    const float* lw    = (const float*)d_in[12];
    const float* lb    = (const float*)d_in[13];
    const float* ow1   = (const float*)d_in[14];
    const float* ob1   = (const float*)d_in[15];
    const float* ow2   = (const float*)d_in[16];
    const float* ob2   = (const float*)d_in[17];
    float* out = (float*)d_out;

    float *ph, *pxt, *pagg, *ptb, *ptab;
    cudaGetSymbolAddress((void**)&ph,   g_h);
    cudaGetSymbolAddress((void**)&pxt,  g_xt);
    cudaGetSymbolAddress((void**)&pagg, g_agg);
    cudaGetSymbolAddress((void**)&ptb,  g_tbuf);
    cudaGetSymbolAddress((void**)&ptab, g_tab);

    // prologue
    zero_kernel<<<1, 256>>>(out, NGRAPH);
    h_init_kernel<<<(NATOMS * 32 + 255) / 256, 256>>>(z, emb);
    edge_d_kernel<<<(NEDGE + 255) / 256, 256>>>(eidx, pos);
    build_tab_kernel<<<(NLAY * TABN) / 8, 256>>>(mw1, mb1, mw2, mb2);

    const int GEMM_BLOCKS = 592;
    const int EDGE_BLOCKS = (NEDGE * 32 + 255) / 256;

    for (int l = 0; l < NLAY; l++) {
        // xt = h @ l1w[l]
        node_gemm<128, 64, false, false><<<GEMM_BLOCKS, 256>>>(
            ph, l1w + l * HDIM * FDIM, nullptr, pxt);
        // agg = 0
        zero_kernel<<<2048, 256>>>(pagg, NPAD * FDIM);
        // agg[dst] += xt[src] * Wtab(d)
        edge_msg_kernel<<<EDGE_BLOCKS, 256>>>(eidx, ptab + l * TABN * FDIM);
        // tbuf = ssp(agg @ l2w[l] + l2b[l])
        node_gemm<64, 128, true, false><<<GEMM_BLOCKS, 256>>>(
            pagg, l2w + l * FDIM * HDIM, l2b + l * HDIM, ptb);
        // h += tbuf @ lw[l] + lb[l]
        node_gemm<128, 128, false, true><<<GEMM_BLOCKS, 256>>>(
            ptb, lw + l * HDIM * HDIM, lb + l * HDIM, ph);
    }

    // output MLP stage 1: xt = ssp(h @ ow1 + ob1)
    node_gemm<128, 64, true, false><<<GEMM_BLOCKS, 256>>>(ph, ow1, ob1, pxt);
    // stage 2 + per-graph segment sum
    readout_kernel<<<(NATOMS * 32 + 255) / 256, 256>>>(ow2, ob2, batch, out);
}

// round 2
// speedup vs baseline: 1.5901x; 1.5901x over previous
#include <cuda_runtime.h>
#include <math.h>

#define NATOMS 50000
#define NPAD   50048          // 64-node tiles
#define NEDGE  1600000
#define HDIM   128
#define FDIM   64
#define GDIM   50
#define NLAY   3
#define NGRAPH 256
#define TABN   4096
#define DMAXV  8.6603f        // > 5*sqrt(3) = max possible distance
#define TSTEP  (DMAXV / (TABN - 1))
#define TINV   ((TABN - 1) / DMAXV)

typedef unsigned long long ull;

// ---- scratch (device globals; no allocation allowed) ----
__device__ float g_h   [NPAD * HDIM];
__device__ float g_xt  [NPAD * FDIM];
__device__ float g_agg [NPAD * FDIM];
__device__ float g_tbuf[NPAD * HDIM];
__device__ float g_u   [NEDGE];
__device__ float g_tab [NLAY * TABN * FDIM];

__device__ __forceinline__ float sspf(float x) {
    float sp = fmaxf(x, 0.0f) + log1pf(__expf(-fabsf(x)));
    return sp - 0.69314718055994531f;
}

// ---- packed f32x2 helpers (FFMA2 is PTX-only on sm_103a) ----
__device__ __forceinline__ ull ffma2(ull a, ull b, ull c) {
    ull d;
    asm("fma.rn.f32x2 %0, %1, %2, %3;" : "=l"(d) : "l"(a), "l"(b), "l"(c));
    return d;
}
__device__ __forceinline__ ull pack2(float x, float y) {
    ull r;
    asm("mov.b64 %0, {%1, %2};" : "=l"(r) : "f"(x), "f"(y));
    return r;
}
__device__ __forceinline__ float2 unpack2(ull v) {
    float2 r;
    asm("mov.b64 {%0, %1}, %2;" : "=f"(r.x), "=f"(r.y) : "l"(v));
    return r;
}

// ---------------- h = emb[z] (pad rows zeroed) ----------------
__global__ void h_init_kernel(const int* __restrict__ z,
                              const float* __restrict__ emb) {
    int i = blockIdx.x * blockDim.x + threadIdx.x;   // one float4 per thread
    if (i >= NPAD * 32) return;
    int n = i >> 5;
    int c = i & 31;
    float4 v = make_float4(0.f, 0.f, 0.f, 0.f);
    if (n < NATOMS) v = ((const float4*)emb)[__ldg(z + n) * 32 + c];
    ((float4*)g_h)[i] = v;
}

// ---------------- per-edge table coordinate u = d * TINV ----------------
__global__ void edge_d_kernel(const int* __restrict__ ei,
                              const float* __restrict__ pos) {
    int e = blockIdx.x * blockDim.x + threadIdx.x;
    if (e >= NEDGE) return;
    int s = __ldg(ei + e);
    int t = __ldg(ei + NEDGE + e);
    float dx = __ldg(pos + s * 3 + 0) - __ldg(pos + t * 3 + 0);
    float dy = __ldg(pos + s * 3 + 1) - __ldg(pos + t * 3 + 1);
    float dz = __ldg(pos + s * 3 + 2) - __ldg(pos + t * 3 + 2);
    g_u[e] = sqrtf(dx * dx + dy * dy + dz * dz) * TINV;
}

// ---------------- filter lookup tables (shared-mem weights) -------------
// grid = (BX, NLAY). Each block stages its layer's weights in shared once,
// then 8 warps each build one table row per iteration.
__global__ void __launch_bounds__(256) build_tab_kernel(
    const float* __restrict__ mw1, const float* __restrict__ mb1,
    const float* __restrict__ mw2, const float* __restrict__ mb2) {
    int layer = blockIdx.y;
    __shared__ float s_w1[GDIM * FDIM];    // 12.8 KB
    __shared__ float s_w2[FDIM * FDIM];    // 16 KB
    __shared__ float s_b1[FDIM], s_b2[FDIM];
    __shared__ float s_g[8][64];
    __shared__ float s_act[8][FDIM];

    int t = threadIdx.x;
    for (int i = t; i < GDIM * FDIM; i += 256)
        s_w1[i] = __ldg(mw1 + layer * GDIM * FDIM + i);
    for (int i = t; i < FDIM * FDIM; i += 256)
        s_w2[i] = __ldg(mw2 + layer * FDIM * FDIM + i);
    if (t < FDIM) {
        s_b1[t] = __ldg(mb1 + layer * FDIM + t);
        s_b2[t] = __ldg(mb2 + layer * FDIM + t);
    }
    __syncthreads();

    int wl = t >> 5, lane = t & 31;
    const float offstep = 10.0f / 49.0f;
    const float coeff   = -0.5f / (offstep * offstep);

    for (int ti = blockIdx.x * 8 + wl; ti < TABN; ti += gridDim.x * 8) {
        float dv = ti * TSTEP;
        for (int g = lane; g < GDIM; g += 32) {
            float x = dv - g * offstep;
            s_g[wl][g] = expf(coeff * x * x);
        }
        __syncwarp();

        // layer 1: G -> F (each lane owns 2 channels)
        ull acc = pack2(s_b1[2 * lane], s_b1[2 * lane + 1]);
        for (int g = 0; g < GDIM; g++) {
            float e = s_g[wl][g];
            ull wv = ((const ull*)(s_w1 + g * FDIM))[lane];
            acc = ffma2(pack2(e, e), wv, acc);
        }
        float2 a = unpack2(acc);
        s_act[wl][2 * lane]     = sspf(a.x);
        s_act[wl][2 * lane + 1] = sspf(a.y);
        __syncwarp();

        // layer 2: F -> F
        ull acc2 = pack2(s_b2[2 * lane], s_b2[2 * lane + 1]);
        for (int f = 0; f < FDIM; f++) {
            float tv = s_act[wl][f];
            ull wv = ((const ull*)(s_w2 + f * FDIM))[lane];
            acc2 = ffma2(pack2(tv, tv), wv, acc2);
        }
        float C = 0.5f * (cosf(dv * 3.14159265358979323846f / 10.0f) + 1.0f);
        float2 c2 = unpack2(acc2);
        float* dst = g_tab + (layer * TABN + ti) * FDIM;
        dst[2 * lane]     = c2.x * C;
        dst[2 * lane + 1] = c2.y * C;
        __syncwarp();
    }
}

// ---------------- zero helper (float4) ----------------
__global__ void zero_kernel(float4* __restrict__ p, int n4) {
    for (int i = blockIdx.x * blockDim.x + threadIdx.x; i < n4;
         i += gridDim.x * blockDim.x)
        p[i] = make_float4(0.f, 0.f, 0.f, 0.f);
}

// ---------------- node GEMM with packed FFMA2 --------------------------
// 64-node tile, 256 threads: og = t&15 covers OPT=OUT/16 outputs,
// np = t>>4 covers 4 nodes. Weights streamed through shared in 32-row chunks.
template <int IN, int OUT, bool ACT, bool RESID>
__global__ void __launch_bounds__(256) node_gemm(
    const float* __restrict__ in, const float* __restrict__ w,
    const float* __restrict__ b, float* __restrict__ out) {
    constexpr int TILE = 64;
    constexpr int KT   = 32;
    constexpr int OPT  = OUT / 16;     // outputs per thread (4 or 8)
    constexpr int OP2  = OPT / 2;      // packed pairs
    constexpr int NCH  = IN / KT;
    constexpr int SIN_STR = IN + 4;

    __shared__ float sw[KT * OUT];
    __shared__ float sin_[TILE * SIN_STR];

    int t  = threadIdx.x;
    int og = t & 15;
    int np = t >> 4;                   // 0..15, 4 nodes each

    ull bias[OP2];
#pragma unroll
    for (int o = 0; o < OP2; o++)
        bias[o] = b ? pack2(__ldg(b + og * OPT + 2 * o),
                            __ldg(b + og * OPT + 2 * o + 1))
                    : 0ull;

    int tile = blockIdx.x;
    {
        const float* inb = in + tile * TILE * IN;
        for (int i = t; i < TILE * IN / 4; i += 256) {
            int n  = i / (IN / 4);
            int k4 = i % (IN / 4);
            ((float4*)(sin_ + n * SIN_STR))[k4] = ((const float4*)inb)[i];
        }

        ull acc[4][OP2];
#pragma unroll
        for (int i = 0; i < 4; i++)
#pragma unroll
            for (int o = 0; o < OP2; o++) acc[i][o] = bias[o];

#pragma unroll 1
        for (int ch = 0; ch < NCH; ch++) {
            __syncthreads();
            for (int i = t; i < KT * OUT / 4; i += 256)
                ((float4*)sw)[i] = ((const float4*)(w + ch * KT * OUT))[i];
            __syncthreads();
#pragma unroll
            for (int k = 0; k < KT; k++) {
                const ull* wr = (const ull*)(sw + k * OUT) + og * OP2;
                ull wv[OP2];
#pragma unroll
                for (int o = 0; o < OP2; o++) wv[o] = wr[o];
#pragma unroll
                for (int i = 0; i < 4; i++) {
                    float a = sin_[(np * 4 + i) * SIN_STR + ch * KT + k];
                    ull pa = pack2(a, a);
#pragma unroll
                    for (int o = 0; o < OP2; o++)
                        acc[i][o] = ffma2(pa, wv[o], acc[i][o]);
                }
            }
        }

#pragma unroll
        for (int i = 0; i < 4; i++) {
            float* op = out + (tile * TILE + np * 4 + i) * OUT + og * OPT;
#pragma unroll
            for (int o = 0; o < OP2; o++) {
                float2 v = unpack2(acc[i][o]);
                if (ACT)  { v.x = sspf(v.x); v.y = sspf(v.y); }
                if (RESID){
                    float2 p = ((const float2*)op)[o];
                    v.x += p.x; v.y += p.y;
                }
                ((float2*)op)[o] = v;
            }
        }
    }
}

// ---------------- edge message + scatter --------------------------------
// 16 lanes per edge, one float4 (4 channels) per lane, vector atomics.
__global__ void __launch_bounds__(256) edge_msg_kernel(
    const int* __restrict__ ei, const float* __restrict__ tab) {
    int gt = blockIdx.x * blockDim.x + threadIdx.x;
    int e  = gt >> 4;
    int c  = gt & 15;
    if (e >= NEDGE) return;

    int s = __ldg(ei + e);
    int t = __ldg(ei + NEDGE + e);
    float u = g_u[e];
    int i0 = min((int)u, TABN - 2);
    float fr = u - (float)i0;

    const float4* tp = ((const float4*)tab) + i0 * 16 + c;
    float4 a  = tp[0];
    float4 bb = tp[16];
    float4 xj = ((const float4*)g_xt)[s * 16 + c];

    float4 m;
    m.x = xj.x * fmaf(fr, bb.x - a.x, a.x);
    m.y = xj.y * fmaf(fr, bb.y - a.y, a.y);
    m.z = xj.z * fmaf(fr, bb.z - a.z, a.z);
    m.w = xj.w * fmaf(fr, bb.w - a.w, a.w);

    atomicAdd(((float4*)g_agg) + t * 16 + c, m);
}

// ---------------- readout: per-node scalar + per-graph atomic sum -------
__global__ void readout_kernel(const float* __restrict__ ow2,
                               const float* __restrict__ ob2,
                               const int* __restrict__ batch,
                               float* __restrict__ out) {
    int gt   = blockIdx.x * blockDim.x + threadIdx.x;
    int n    = gt >> 5;
    int lane = gt & 31;
    if (n >= NATOMS) return;
    float2 v = ((const float2*)g_xt)[n * 32 + lane];
    float2 w = ((const float2*)ow2)[lane];
    float s = v.x * w.x + v.y * w.y;
#pragma unroll
    for (int off = 16; off; off >>= 1)
        s += __shfl_down_sync(0xffffffffu, s, off);
    if (lane == 0)
        atomicAdd(out + __ldg(batch + n), s + __ldg(ob2));
}

extern "C" void kernel_launch(void* const* d_in, const int* in_sizes, int n_in,
                              void* d_out, int out_size) {
    const int*   z     = (const int*)  d_in[0];
    const float* pos   = (const float*)d_in[1];
    const int*   batch = (const int*)  d_in[2];
    const int*   eidx  = (const int*)  d_in[3];
    const float* emb   = (const float*)d_in[4];
    const float* mw1   = (const float*)d_in[5];
    const float* mb1   = (const float*)d_in[6];
    const float* mw2   = (const float*)d_in[7];
    const float* mb2   = (const float*)d_in[8];
    const float* l1w   = (const float*)d_in[9];
    const float* l2w   = (const float*)d_in[10];
    const float* l2b   = (const float*)d_in[11];
    const float* lw    = (const float*)d_in[12];
    const float* lb    = (const float*)d_in[13];
    const float* ow1   = (const float*)d_in[14];
    const float* ob1   = (const float*)d_in[15];
    const float* ow2   = (const float*)d_in[16];
    const float* ob2   = (const float*)d_in[17];
    float* out = (float*)d_out;

    float *ph, *pxt, *pagg, *ptb, *ptab;
    cudaGetSymbolAddress((void**)&ph,   g_h);
    cudaGetSymbolAddress((void**)&pxt,  g_xt);
    cudaGetSymbolAddress((void**)&pagg, g_agg);
    cudaGetSymbolAddress((void**)&ptb,  g_tbuf);
    cudaGetSymbolAddress((void**)&ptab, g_tab);

    // prologue
    zero_kernel<<<1, 64>>>((float4*)out, NGRAPH / 4);
    h_init_kernel<<<(NPAD * 32 + 255) / 256, 256>>>(z, emb);
    edge_d_kernel<<<(NEDGE + 255) / 256, 256>>>(eidx, pos);
    {
        dim3 g(64, NLAY);
        build_tab_kernel<<<g, 256>>>(mw1, mb1, mw2, mb2);
    }

    const int NTILES = NPAD / 64;                        // 782
    const int EDGE_BLOCKS = (NEDGE * 16 + 255) / 256;    // 100000

    for (int l = 0; l < NLAY; l++) {
        // xt = h @ l1w[l]
        node_gemm<128, 64, false, false><<<NTILES, 256>>>(
            ph, l1w + l * HDIM * FDIM, nullptr, pxt);
        // agg = 0
        zero_kernel<<<1184, 256>>>((float4*)pagg, NPAD * FDIM / 4);
        // agg[dst] += xt[src] * Wtab(d)
        edge_msg_kernel<<<EDGE_BLOCKS, 256>>>(eidx, ptab + l * TABN * FDIM);
        // tbuf = ssp(agg @ l2w[l] + l2b[l])
        node_gemm<64, 128, true, false><<<NTILES, 256>>>(
            pagg, l2w + l * FDIM * HDIM, l2b + l * HDIM, ptb);
        // h += tbuf @ lw[l] + lb[l]
        node_gemm<128, 128, false, true><<<NTILES, 256>>>(
            ptb, lw + l * HDIM * HDIM, lb + l * HDIM, ph);
    }

    // output MLP stage 1: xt = ssp(h @ ow1 + ob1)
    node_gemm<128, 64, true, false><<<NTILES, 256>>>(ph, ow1, ob1, pxt);
    // stage 2 + per-graph segment sum
    readout_kernel<<<(NATOMS * 32 + 255) / 256, 256>>>(ow2, ob2, batch, out);
}

// round 3
// speedup vs baseline: 1.7987x; 1.1312x over previous
#include <cuda_runtime.h>
#include <cuda_fp16.h>
#include <math.h>

#define NATOMS 50000
#define NPAD   50048          // 64-node tiles
#define NEDGE  1600000
#define HDIM   128
#define FDIM   64
#define GDIM   50
#define NLAY   3
#define NGRAPH 256
#define TABN   4096
#define DMAXV  8.6603f        // > 5*sqrt(3) = max possible distance
#define TSTEP  (DMAXV / (TABN - 1))
#define TINV   ((TABN - 1) / DMAXV)

#define SCAN_B 512
#define NCHUNK ((NPAD + SCAN_B - 1) / SCAN_B)   // 98

typedef unsigned long long ull;

// ---- scratch (device globals; no allocation allowed) ----
__device__ float   g_h    [NPAD * HDIM];
__device__ float   g_xt   [NPAD * FDIM];
__device__ __half2 g_xth  [NPAD * FDIM / 2];
__device__ float   g_agg  [NPAD * FDIM];
__device__ float   g_tbuf [NPAD * HDIM];
__device__ float   g_u    [NEDGE];
__device__ __half2 g_tabh [NLAY * TABN * FDIM / 2];
__device__ int     g_deg  [NPAD];
__device__ int     g_rowptr[NPAD + 1];
__device__ int     g_cursor[NPAD];
__device__ int     g_part [NCHUNK];
__device__ float2  g_erec [NEDGE];     // {src_as_float, u}

__device__ __forceinline__ float sspf(float x) {
    float sp = fmaxf(x, 0.0f) + log1pf(__expf(-fabsf(x)));
    return sp - 0.69314718055994531f;
}

// ---- packed f32x2 helpers (FFMA2 is PTX-only on sm_103a) ----
__device__ __forceinline__ ull ffma2(ull a, ull b, ull c) {
    ull d;
    asm("fma.rn.f32x2 %0, %1, %2, %3;" : "=l"(d) : "l"(a), "l"(b), "l"(c));
    return d;
}
__device__ __forceinline__ ull pack2(float x, float y) {
    ull r;
    asm("mov.b64 %0, {%1, %2};" : "=l"(r) : "f"(x), "f"(y));
    return r;
}
__device__ __forceinline__ float2 unpack2(ull v) {
    float2 r;
    asm("mov.b64 {%0, %1}, %2;" : "=f"(r.x), "=f"(r.y) : "l"(v));
    return r;
}

// ---------------- h = emb[z] (pad rows zeroed) ----------------
__global__ void h_init_kernel(const int* __restrict__ z,
                              const float* __restrict__ emb) {
    int i = blockIdx.x * blockDim.x + threadIdx.x;
    if (i >= NPAD * 32) return;
    int n = i >> 5;
    int c = i & 31;
    float4 v = make_float4(0.f, 0.f, 0.f, 0.f);
    if (n < NATOMS) v = ((const float4*)emb)[__ldg(z + n) * 32 + c];
    ((float4*)g_h)[i] = v;
}

// ---------------- per-edge table coordinate u = d * TINV, + degree ------
__global__ void edge_d_kernel(const int* __restrict__ ei,
                              const float* __restrict__ pos) {
    int e = blockIdx.x * blockDim.x + threadIdx.x;
    if (e >= NEDGE) return;
    int s = __ldg(ei + e);
    int t = __ldg(ei + NEDGE + e);
    float dx = __ldg(pos + s * 3 + 0) - __ldg(pos + t * 3 + 0);
    float dy = __ldg(pos + s * 3 + 1) - __ldg(pos + t * 3 + 1);
    float dz = __ldg(pos + s * 3 + 2) - __ldg(pos + t * 3 + 2);
    g_u[e] = sqrtf(dx * dx + dy * dy + dz * dz) * TINV;
    atomicAdd(&g_deg[t], 1);
}

// ---------------- CSR scan: per-chunk partial sums ----------------------
__global__ void __launch_bounds__(SCAN_B) part_sum_kernel() {
    __shared__ int sh[SCAN_B];
    int idx = blockIdx.x * SCAN_B + threadIdx.x;
    int v = (idx < NPAD) ? g_deg[idx] : 0;
    sh[threadIdx.x] = v;
    __syncthreads();
    for (int s = SCAN_B / 2; s > 0; s >>= 1) {
        if (threadIdx.x < s) sh[threadIdx.x] += sh[threadIdx.x + s];
        __syncthreads();
    }
    if (threadIdx.x == 0) g_part[blockIdx.x] = sh[0];
}

// ---------------- CSR scan: spine (serial, tiny) ------------------------
__global__ void spine_kernel() {
    if (threadIdx.x == 0) {
        int acc = 0;
        for (int i = 0; i < NCHUNK; i++) {
            int v = g_part[i];
            g_part[i] = acc;
            acc += v;
        }
        g_rowptr[NPAD] = NEDGE;
    }
}

// ---------------- CSR scan: write rowptr + cursor -----------------------
__global__ void __launch_bounds__(SCAN_B) scan_write_kernel() {
    __shared__ int sh[SCAN_B];
    int idx = blockIdx.x * SCAN_B + threadIdx.x;
    int own = (idx < NPAD) ? g_deg[idx] : 0;
    sh[threadIdx.x] = own;
    __syncthreads();
    // Hillis-Steele inclusive scan
    for (int s = 1; s < SCAN_B; s <<= 1) {
        int v = (threadIdx.x >= s) ? sh[threadIdx.x - s] : 0;
        __syncthreads();
        sh[threadIdx.x] += v;
        __syncthreads();
    }
    if (idx < NPAD) {
        int excl = g_part[blockIdx.x] + sh[threadIdx.x] - own;
        g_rowptr[idx] = excl;
        g_cursor[idx] = excl;
    }
}

// ---------------- CSR scatter: pack {src, u} records --------------------
__global__ void scatter_kernel(const int* __restrict__ ei) {
    int e = blockIdx.x * blockDim.x + threadIdx.x;
    if (e >= NEDGE) return;
    int s = __ldg(ei + e);
    int t = __ldg(ei + NEDGE + e);
    int slot = atomicAdd(&g_cursor[t], 1);
    g_erec[slot] = make_float2(__int_as_float(s), g_u[e]);
}

// ---------------- filter lookup tables (shared-mem weights, fp16 out) ---
__global__ void __launch_bounds__(256) build_tab_kernel(
    const float* __restrict__ mw1, const float* __restrict__ mb1,
    const float* __restrict__ mw2, const float* __restrict__ mb2) {
    int layer = blockIdx.y;
    __shared__ float s_w1[GDIM * FDIM];
    __shared__ float s_w2[FDIM * FDIM];
    __shared__ float s_b1[FDIM], s_b2[FDIM];
    __shared__ float s_g[8][64];
    __shared__ float s_act[8][FDIM];

    int t = threadIdx.x;
    for (int i = t; i < GDIM * FDIM; i += 256)
        s_w1[i] = __ldg(mw1 + layer * GDIM * FDIM + i);
    for (int i = t; i < FDIM * FDIM; i += 256)
        s_w2[i] = __ldg(mw2 + layer * FDIM * FDIM + i);
    if (t < FDIM) {
        s_b1[t] = __ldg(mb1 + layer * FDIM + t);
        s_b2[t] = __ldg(mb2 + layer * FDIM + t);
    }
    __syncthreads();

    int wl = t >> 5, lane = t & 31;
    const float offstep = 10.0f / 49.0f;
    const float coeff   = -0.5f / (offstep * offstep);

    for (int ti = blockIdx.x * 8 + wl; ti < TABN; ti += gridDim.x * 8) {
        float dv = ti * TSTEP;
        for (int g = lane; g < GDIM; g += 32) {
            float x = dv - g * offstep;
            s_g[wl][g] = expf(coeff * x * x);
        }
        __syncwarp();

        ull acc = pack2(s_b1[2 * lane], s_b1[2 * lane + 1]);
        for (int g = 0; g < GDIM; g++) {
            float e = s_g[wl][g];
            ull wv = ((const ull*)(s_w1 + g * FDIM))[lane];
            acc = ffma2(pack2(e, e), wv, acc);
        }
        float2 a = unpack2(acc);
        s_act[wl][2 * lane]     = sspf(a.x);
        s_act[wl][2 * lane + 1] = sspf(a.y);
        __syncwarp();

        ull acc2 = pack2(s_b2[2 * lane], s_b2[2 * lane + 1]);
        for (int f = 0; f < FDIM; f++) {
            float tv = s_act[wl][f];
            ull wv = ((const ull*)(s_w2 + f * FDIM))[lane];
            acc2 = ffma2(pack2(tv, tv), wv, acc2);
        }
        float C = 0.5f * (cosf(dv * 3.14159265358979323846f / 10.0f) + 1.0f);
        float2 c2 = unpack2(acc2);
        g_tabh[(layer * TABN + ti) * 32 + lane] =
            __floats2half2_rn(c2.x * C, c2.y * C);
        __syncwarp();
    }
}

// ---------------- zero helper (float4) ----------------
__global__ void zero_kernel(float4* __restrict__ p, int n4) {
    for (int i = blockIdx.x * blockDim.x + threadIdx.x; i < n4;
         i += gridDim.x * blockDim.x)
        p[i] = make_float4(0.f, 0.f, 0.f, 0.f);
}

// ---------------- node GEMM with packed FFMA2 --------------------------
template <int IN, int OUT, bool ACT, bool RESID, bool HOUT>
__global__ void __launch_bounds__(256) node_gemm(
    const float* __restrict__ in, const float* __restrict__ w,
    const float* __restrict__ b, float* __restrict__ out) {
    constexpr int TILE = 64;
    constexpr int KT   = 32;
    constexpr int OPT  = OUT / 16;
    constexpr int OP2  = OPT / 2;
    constexpr int NCH  = IN / KT;
    constexpr int SIN_STR = IN + 4;

    __shared__ float sw[KT * OUT];
    __shared__ float sin_[TILE * SIN_STR];

    int t  = threadIdx.x;
    int og = t & 15;
    int np = t >> 4;

    ull bias[OP2];
#pragma unroll
    for (int o = 0; o < OP2; o++)
        bias[o] = b ? pack2(__ldg(b + og * OPT + 2 * o),
                            __ldg(b + og * OPT + 2 * o + 1))
                    : 0ull;

    int tile = blockIdx.x;
    const float* inb = in + tile * TILE * IN;
    for (int i = t; i < TILE * IN / 4; i += 256) {
        int n  = i / (IN / 4);
        int k4 = i % (IN / 4);
        ((float4*)(sin_ + n * SIN_STR))[k4] = ((const float4*)inb)[i];
    }

    ull acc[4][OP2];
#pragma unroll
    for (int i = 0; i < 4; i++)
#pragma unroll
        for (int o = 0; o < OP2; o++) acc[i][o] = bias[o];

#pragma unroll 1
    for (int ch = 0; ch < NCH; ch++) {
        __syncthreads();
        for (int i = t; i < KT * OUT / 4; i += 256)
            ((float4*)sw)[i] = ((const float4*)(w + ch * KT * OUT))[i];
        __syncthreads();
#pragma unroll
        for (int k = 0; k < KT; k++) {
            const ull* wr = (const ull*)(sw + k * OUT) + og * OP2;
            ull wv[OP2];
#pragma unroll
            for (int o = 0; o < OP2; o++) wv[o] = wr[o];
#pragma unroll
            for (int i = 0; i < 4; i++) {
                float a = sin_[(np * 4 + i) * SIN_STR + ch * KT + k];
                ull pa = pack2(a, a);
#pragma unroll
                for (int o = 0; o < OP2; o++)
                    acc[i][o] = ffma2(pa, wv[o], acc[i][o]);
            }
        }
    }

#pragma unroll
    for (int i = 0; i < 4; i++) {
        int node = tile * TILE + np * 4 + i;
#pragma unroll
        for (int o = 0; o < OP2; o++) {
            float2 v = unpack2(acc[i][o]);
            if (ACT)  { v.x = sspf(v.x); v.y = sspf(v.y); }
            if (RESID){
                float2 p = ((const float2*)(out + node * OUT + og * OPT))[o];
                v.x += p.x; v.y += p.y;
            }
            if (HOUT) {
                ((__half2*)out)[node * (OUT / 2) + og * OP2 + o] =
                    __floats2half2_rn(v.x, v.y);
            } else {
                ((float2*)(out + node * OUT + og * OPT))[o] = v;
            }
        }
    }
}

// ---------------- gather aggregation: warp per node ---------------------
__global__ void __launch_bounds__(256) gather_kernel(
    const __half2* __restrict__ tab) {
    int gw   = (blockIdx.x * blockDim.x + threadIdx.x) >> 5;
    int lane = threadIdx.x & 31;
    if (gw >= NPAD) return;

    int beg = 0, end = 0;
    if (lane == 0) {
        beg = g_rowptr[gw];
        end = g_rowptr[gw + 1];
    }
    beg = __shfl_sync(0xffffffffu, beg, 0);
    end = __shfl_sync(0xffffffffu, end, 0);

    float2 acc = make_float2(0.f, 0.f);
    for (int i = beg; i < end; i++) {
        float2 rec = __ldg(&g_erec[i]);
        int   s  = __float_as_int(rec.x);
        float u  = rec.y;
        int   i0 = min((int)u, TABN - 2);
        float fr = u - (float)i0;

        float2 fa = __half22float2(__ldg(tab + i0 * 32 + lane));
        float2 fb = __half22float2(__ldg(tab + i0 * 32 + 32 + lane));
        float2 fx = __half22float2(__ldg(&g_xth[s * 32 + lane]));

        float wx = fmaf(fr, fb.x - fa.x, fa.x);
        float wy = fmaf(fr, fb.y - fa.y, fa.y);
        acc.x = fmaf(fx.x, wx, acc.x);
        acc.y = fmaf(fx.y, wy, acc.y);
    }
    ((float2*)g_agg)[gw * 32 + lane] = acc;
}

// ---------------- readout: per-node scalar + per-graph atomic sum -------
__global__ void readout_kernel(const float* __restrict__ ow2,
                               const float* __restrict__ ob2,
                               const int* __restrict__ batch,
                               float* __restrict__ out) {
    int gt   = blockIdx.x * blockDim.x + threadIdx.x;
    int n    = gt >> 5;
    int lane = gt & 31;
    if (n >= NATOMS) return;
    float2 v = ((const float2*)g_xt)[n * 32 + lane];
    float2 w = ((const float2*)ow2)[lane];
    float s = v.x * w.x + v.y * w.y;
#pragma unroll
    for (int off = 16; off; off >>= 1)
        s += __shfl_down_sync(0xffffffffu, s, off);
    if (lane == 0)
        atomicAdd(out + __ldg(batch + n), s + __ldg(ob2));
}

extern "C" void kernel_launch(void* const* d_in, const int* in_sizes, int n_in,
                              void* d_out, int out_size) {
    const int*   z     = (const int*)  d_in[0];
    const float* pos   = (const float*)d_in[1];
    const int*   batch = (const int*)  d_in[2];
    const int*   eidx  = (const int*)  d_in[3];
    const float* emb   = (const float*)d_in[4];
    const float* mw1   = (const float*)d_in[5];
    const float* mb1   = (const float*)d_in[6];
    const float* mw2   = (const float*)d_in[7];
    const float* mb2   = (const float*)d_in[8];
    const float* l1w   = (const float*)d_in[9];
    const float* l2w   = (const float*)d_in[10];
    const float* l2b   = (const float*)d_in[11];
    const float* lw    = (const float*)d_in[12];
    const float* lb    = (const float*)d_in[13];
    const float* ow1   = (const float*)d_in[14];
    const float* ob1   = (const float*)d_in[15];
    const float* ow2   = (const float*)d_in[16];
    const float* ob2   = (const float*)d_in[17];
    float* out = (float*)d_out;

    float *ph, *pxt, *pagg, *ptb, *pdeg;
    __half2 *pxth, *ptabh;
    cudaGetSymbolAddress((void**)&ph,    g_h);
    cudaGetSymbolAddress((void**)&pxt,   g_xt);
    cudaGetSymbolAddress((void**)&pxth,  g_xth);
    cudaGetSymbolAddress((void**)&pagg,  g_agg);
    cudaGetSymbolAddress((void**)&ptb,   g_tbuf);
    cudaGetSymbolAddress((void**)&ptabh, g_tabh);
    cudaGetSymbolAddress((void**)&pdeg,  g_deg);

    // prologue
    zero_kernel<<<1, 64>>>((float4*)out, NGRAPH / 4);
    zero_kernel<<<64, 256>>>((float4*)pdeg, NPAD / 4);
    h_init_kernel<<<(NPAD * 32 + 255) / 256, 256>>>(z, emb);
    edge_d_kernel<<<(NEDGE + 255) / 256, 256>>>(eidx, pos);
    // CSR build
    part_sum_kernel<<<NCHUNK, SCAN_B>>>();
    spine_kernel<<<1, 32>>>();
    scan_write_kernel<<<NCHUNK, SCAN_B>>>();
    scatter_kernel<<<(NEDGE + 255) / 256, 256>>>(eidx);
    // filter tables
    {
        dim3 g(192, NLAY);
        build_tab_kernel<<<g, 256>>>(mw1, mb1, mw2, mb2);
    }

    const int NTILES = NPAD / 64;                        // 782
    const int GATHER_BLOCKS = (NPAD * 32 + 255) / 256;   // 6256

    for (int l = 0; l < NLAY; l++) {
        // xth = h @ l1w[l]  (fp16 output for gather)
        node_gemm<128, 64, false, false, true><<<NTILES, 256>>>(
            ph, l1w + l * HDIM * FDIM, nullptr, (float*)pxth);
        // agg[n] = sum over incoming edges (CSR gather, no atomics)
        gather_kernel<<<GATHER_BLOCKS, 256>>>(ptabh + l * TABN * 32);
        // tbuf = ssp(agg @ l2w[l] + l2b[l])
        node_gemm<64, 128, true, false, false><<<NTILES, 256>>>(
            pagg, l2w + l * FDIM * HDIM, l2b + l * HDIM, ptb);
        // h += tbuf @ lw[l] + lb[l]
        node_gemm<128, 128, false, true, false><<<NTILES, 256>>>(
            ptb, lw + l * HDIM * HDIM, lb + l * HDIM, ph);
    }

    // output MLP stage 1: xt = ssp(h @ ow1 + ob1)
    node_gemm<128, 64, true, false, false><<<NTILES, 256>>>(ph, ow1, ob1, pxt);
    // stage 2 + per-graph segment sum
    readout_kernel<<<(NATOMS * 32 + 255) / 256, 256>>>(ow2, ob2, batch, out);
}